// round 1
// baseline (speedup 1.0000x reference)
#include <cuda_runtime.h>
#include <math.h>

// ---------------- problem constants ----------------
#define BT_   1024          // batch
#define CH_   3
#define AW_   64            // image width  (a)
#define BH_   64            // image height (y)
#define NF_   16            // filter grid
#define HD_   1024          // hidden
#define IN_   768           // N*N*C
#define GATE_ 4096          // 4*H
#define TSTEPS_ 16

// ---------------- persistent scratch (device globals; no allocs) ----------------
__device__ float g_h[BT_ * HD_];
__device__ float g_c[BT_ * HD_];
__device__ float g_r[BT_ * IN_];
__device__ float g_gates[BT_ * GATE_];
__device__ float g_Fx[BT_ * NF_ * AW_];
__device__ float g_Fy[BT_ * NF_ * BH_];
__device__ float g_gamma[BT_];
__device__ float g_t[BT_ * HD_];

// ---------------- zero h and c ----------------
__global__ void zero_hc_kernel() {
    int i = blockIdx.x * blockDim.x + threadIdx.x;
    if (i < BT_ * HD_) { g_h[i] = 0.f; g_c[i] = 0.f; }
}

// ---------------- attention params + filterbanks ----------------
// one block per batch element, 256 threads
__global__ void att_kernel(const float* __restrict__ h,
                           const float* __restrict__ W_att,
                           const float* __restrict__ b_att,
                           float* __restrict__ Fx,
                           float* __restrict__ Fy,
                           float* __restrict__ gamma) {
    const int b   = blockIdx.x;
    const int tid = threadIdx.x;

    __shared__ float red[5][256];
    __shared__ float params[5];
    __shared__ float F[16][64];
    __shared__ float rnorm[16];

    // p = h[b] @ W_att.T  (5 dot products of length 1024)
    float a0 = 0.f, a1 = 0.f, a2 = 0.f, a3 = 0.f, a4 = 0.f;
    const float* hb = h + b * HD_;
    for (int k = tid; k < HD_; k += 256) {
        float hv = hb[k];
        a0 += hv * W_att[0 * HD_ + k];
        a1 += hv * W_att[1 * HD_ + k];
        a2 += hv * W_att[2 * HD_ + k];
        a3 += hv * W_att[3 * HD_ + k];
        a4 += hv * W_att[4 * HD_ + k];
    }
    red[0][tid] = a0; red[1][tid] = a1; red[2][tid] = a2; red[3][tid] = a3; red[4][tid] = a4;
    __syncthreads();
    for (int s = 128; s > 0; s >>= 1) {
        if (tid < s) {
            #pragma unroll
            for (int j = 0; j < 5; j++) red[j][tid] += red[j][tid + s];
        }
        __syncthreads();
    }
    if (tid < 5) params[tid] = red[tid][0] + b_att[tid];
    __syncthreads();

    const float gx     = 32.5f * (params[0] + 1.0f);          // (A+1)/2 * (gx_+1)
    const float gy     = 32.5f * (params[1] + 1.0f);
    const float sigma2 = expf(params[2]);
    const float delta  = (63.0f / 15.0f) * expf(params[3]);   // (max(A,B)-1)/(N-1)*exp
    if (tid == 0) gamma[b] = expf(params[4]);
    const float inv2s = 1.0f / (2.0f * sigma2);

    // ---- Fx (x-direction filterbank over a) ----
    for (int idx = tid; idx < NF_ * AW_; idx += 256) {
        int i = idx >> 6, a = idx & 63;
        float mu = gx + ((float)i - 8.5f) * delta;   // grid - N/2 - 0.5
        float d  = (float)a - mu;
        F[i][a]  = expf(-d * d * inv2s);
    }
    __syncthreads();
    if (tid < 16) {
        float s = 0.f;
        for (int a = 0; a < 64; a++) s += F[tid][a];
        rnorm[tid] = 1.0f / (s + 1e-8f);
    }
    __syncthreads();
    for (int idx = tid; idx < NF_ * AW_; idx += 256) {
        int i = idx >> 6, a = idx & 63;
        Fx[b * NF_ * AW_ + idx] = F[i][a] * rnorm[i];
    }
    __syncthreads();

    // ---- Fy (y-direction filterbank over b-rows) ----
    for (int idx = tid; idx < NF_ * BH_; idx += 256) {
        int i = idx >> 6, a = idx & 63;
        float mu = gy + ((float)i - 8.5f) * delta;
        float d  = (float)a - mu;
        F[i][a]  = expf(-d * d * inv2s);
    }
    __syncthreads();
    if (tid < 16) {
        float s = 0.f;
        for (int a = 0; a < 64; a++) s += F[tid][a];
        rnorm[tid] = 1.0f / (s + 1e-8f);
    }
    __syncthreads();
    for (int idx = tid; idx < NF_ * BH_; idx += 256) {
        int i = idx >> 6, a = idx & 63;
        Fy[b * NF_ * BH_ + idx] = F[i][a] * rnorm[i];
    }
}

// ---------------- glimpse: r[b] = gamma * (Fy @ img_c @ Fx^T).flatten ----------------
// one block per batch element, 256 threads
__global__ void glimpse_kernel(const float* __restrict__ x,
                               const float* __restrict__ Fx,
                               const float* __restrict__ Fy,
                               const float* __restrict__ gamma,
                               float* __restrict__ r) {
    const int b   = blockIdx.x;
    const int tid = threadIdx.x;

    __shared__ float sFy[NF_ * BH_];    // [n][y]
    __shared__ float sFx[NF_][AW_ + 1]; // padded vs bank conflicts
    __shared__ float simg[BH_ * AW_];   // one channel
    __shared__ float stmp[NF_ * AW_];   // [n][a]

    for (int idx = tid; idx < NF_ * BH_; idx += 256) sFy[idx] = Fy[b * NF_ * BH_ + idx];
    for (int idx = tid; idx < NF_ * AW_; idx += 256) {
        int i = idx >> 6, a = idx & 63;
        sFx[i][a] = Fx[b * NF_ * AW_ + idx];
    }
    const float gam = gamma[b];

    for (int c = 0; c < CH_; c++) {
        __syncthreads();
        // load channel image
        const float* xc = x + ((size_t)(b * CH_ + c)) * (BH_ * AW_);
        for (int idx = tid; idx < BH_ * AW_; idx += 256) simg[idx] = xc[idx];
        __syncthreads();
        // tmp[n][a] = sum_y Fy[n][y] * img[y][a]
        for (int idx = tid; idx < NF_ * AW_; idx += 256) {
            int n = idx >> 6, a = idx & 63;
            float s = 0.f;
            #pragma unroll 8
            for (int y = 0; y < BH_; y++) s += sFy[n * BH_ + y] * simg[y * AW_ + a];
            stmp[idx] = s;
        }
        __syncthreads();
        // glimpse[n][xo] = sum_a tmp[n][a] * Fx[xo][a]
        {
            int n = tid >> 4, xo = tid & 15;
            float s = 0.f;
            #pragma unroll 8
            for (int a = 0; a < AW_; a++) s += stmp[n * AW_ + a] * sFx[xo][a];
            r[b * IN_ + c * (NF_ * NF_) + n * NF_ + xo] = s * gam;
        }
    }
}

// ---------------- tiled fp32 GEMM: C = A0 @ W0^T (+ A1 @ W1^T) + bias (+relu) ----------------
// A row-major (M x K), W row-major (N x K), C row-major (M x N)
// BM=BN=128, BK=16, 256 threads, 8x8 microtile
template <bool RELU, bool TWO>
__global__ __launch_bounds__(256, 2)
void gemm_nt(const float* __restrict__ A0, int K0, const float* __restrict__ W0,
             const float* __restrict__ A1, int K1, const float* __restrict__ W1,
             const float* __restrict__ bias0, const float* __restrict__ bias1,
             float* __restrict__ C, int M, int Nn) {
    __shared__ float As[16][128];
    __shared__ float Bs[16][128];

    const int tid = threadIdx.x;
    const int m0  = blockIdx.y * 128;
    const int n0  = blockIdx.x * 128;
    const int tx  = tid & 15;   // col group
    const int ty  = tid >> 4;   // row group
    const int lrow = tid >> 1;         // 0..127
    const int lq   = (tid & 1) * 2;    // 0 or 2 (float4 index base)

    float acc[8][8];
    #pragma unroll
    for (int i = 0; i < 8; i++)
        #pragma unroll
        for (int j = 0; j < 8; j++) acc[i][j] = 0.f;

    const int KT = TWO ? (K0 + K1) : K0;
    for (int kt = 0; kt < KT; kt += 16) {
        const float* Ap; const float* Wp; int kk; int ld;
        if (!TWO || kt < K0) { Ap = A0; Wp = W0; kk = kt;      ld = K0; }
        else                 { Ap = A1; Wp = W1; kk = kt - K0; ld = K1; }

        #pragma unroll
        for (int qq = 0; qq < 2; qq++) {
            int q = lq + qq;
            float4 va = *reinterpret_cast<const float4*>(Ap + (m0 + lrow) * ld + kk + q * 4);
            As[q * 4 + 0][lrow] = va.x;
            As[q * 4 + 1][lrow] = va.y;
            As[q * 4 + 2][lrow] = va.z;
            As[q * 4 + 3][lrow] = va.w;
            float4 vb = *reinterpret_cast<const float4*>(Wp + (n0 + lrow) * ld + kk + q * 4);
            Bs[q * 4 + 0][lrow] = vb.x;
            Bs[q * 4 + 1][lrow] = vb.y;
            Bs[q * 4 + 2][lrow] = vb.z;
            Bs[q * 4 + 3][lrow] = vb.w;
        }
        __syncthreads();

        #pragma unroll
        for (int k = 0; k < 16; k++) {
            float ra[8], rb[8];
            #pragma unroll
            for (int i = 0; i < 8; i++) ra[i] = As[k][ty * 8 + i];
            #pragma unroll
            for (int j = 0; j < 8; j++) rb[j] = Bs[k][tx * 8 + j];
            #pragma unroll
            for (int i = 0; i < 8; i++)
                #pragma unroll
                for (int j = 0; j < 8; j++) acc[i][j] += ra[i] * rb[j];
        }
        __syncthreads();
    }

    // epilogue: bias (+bias1) (+relu), vectorized stores
    #pragma unroll
    for (int i = 0; i < 8; i++) {
        int m = m0 + ty * 8 + i;
        #pragma unroll
        for (int jv = 0; jv < 2; jv++) {
            int n = n0 + tx * 8 + jv * 4;
            float4 v;
            float* vp = &v.x;
            #pragma unroll
            for (int u = 0; u < 4; u++) {
                float t = acc[i][jv * 4 + u] + bias0[n + u];
                if (TWO)  t += bias1[n + u];
                if (RELU) t = fmaxf(t, 0.f);
                vp[u] = t;
            }
            *reinterpret_cast<float4*>(C + (size_t)m * Nn + n) = v;
        }
    }
}

// ---------------- LSTM pointwise update ----------------
__global__ void lstm_kernel(const float* __restrict__ gates,
                            float* __restrict__ c, float* __restrict__ h) {
    int idx = blockIdx.x * blockDim.x + threadIdx.x;
    if (idx >= BT_ * HD_) return;
    int b = idx >> 10, j = idx & 1023;
    const float* g = gates + b * GATE_;
    float ig = g[j];
    float fg = g[HD_ + j];
    float gg = g[2 * HD_ + j];
    float og = g[3 * HD_ + j];
    float si = 1.f / (1.f + expf(-ig));
    float sf = 1.f / (1.f + expf(-fg));
    float so = 1.f / (1.f + expf(-og));
    float tg = tanhf(gg);
    float cn = sf * c[idx] + si * tg;
    c[idx] = cn;
    h[idx] = so * tanhf(cn);
}

// ---------------- final small fc: out = t @ W_fc^T + b_fc  (N=10) ----------------
// one block per batch row, 10 warps, one warp per output
__global__ void fc_kernel(const float* __restrict__ t,
                          const float* __restrict__ W_fc,
                          const float* __restrict__ b_fc,
                          float* __restrict__ out) {
    int b    = blockIdx.x;
    int w    = threadIdx.x >> 5;
    int lane = threadIdx.x & 31;
    const float* tb = t + b * HD_;
    const float* wr = W_fc + w * HD_;
    float s = 0.f;
    for (int k = lane; k < HD_; k += 32) s += tb[k] * wr[k];
    #pragma unroll
    for (int off = 16; off; off >>= 1) s += __shfl_down_sync(0xffffffffu, s, off);
    if (lane == 0) out[b * 10 + w] = s + b_fc[w];
}

// ---------------- host launch ----------------
extern "C" void kernel_launch(void* const* d_in, const int* in_sizes, int n_in,
                              void* d_out, int out_size) {
    const float* x     = (const float*)d_in[0];
    const float* W_att = (const float*)d_in[1];
    const float* b_att = (const float*)d_in[2];
    const float* W_ih  = (const float*)d_in[3];
    const float* W_hh  = (const float*)d_in[4];
    const float* b_ih  = (const float*)d_in[5];
    const float* b_hh  = (const float*)d_in[6];
    const float* W_fc0 = (const float*)d_in[7];
    const float* b_fc0 = (const float*)d_in[8];
    const float* W_fc  = (const float*)d_in[9];
    const float* b_fc  = (const float*)d_in[10];
    float* out = (float*)d_out;

    static float *p_h = nullptr, *p_c, *p_r, *p_gates, *p_Fx, *p_Fy, *p_gamma, *p_t;
    if (!p_h) {
        cudaGetSymbolAddress((void**)&p_h,     g_h);
        cudaGetSymbolAddress((void**)&p_c,     g_c);
        cudaGetSymbolAddress((void**)&p_r,     g_r);
        cudaGetSymbolAddress((void**)&p_gates, g_gates);
        cudaGetSymbolAddress((void**)&p_Fx,    g_Fx);
        cudaGetSymbolAddress((void**)&p_Fy,    g_Fy);
        cudaGetSymbolAddress((void**)&p_gamma, g_gamma);
        cudaGetSymbolAddress((void**)&p_t,     g_t);
    }

    zero_hc_kernel<<<(BT_ * HD_ + 255) / 256, 256>>>();

    for (int step = 0; step < TSTEPS_; step++) {
        att_kernel<<<BT_, 256>>>(p_h, W_att, b_att, p_Fx, p_Fy, p_gamma);
        glimpse_kernel<<<BT_, 256>>>(x, p_Fx, p_Fy, p_gamma, p_r);
        gemm_nt<false, true><<<dim3(GATE_ / 128, BT_ / 128), 256>>>(
            p_r, IN_, W_ih, p_h, HD_, W_hh, b_ih, b_hh, p_gates, BT_, GATE_);
        lstm_kernel<<<(BT_ * HD_) / 256, 256>>>(p_gates, p_c, p_h);
    }

    gemm_nt<true, false><<<dim3(HD_ / 128, BT_ / 128), 256>>>(
        p_h, HD_, W_fc0, nullptr, 0, nullptr, b_fc0, nullptr, p_t, BT_, HD_);

    fc_kernel<<<BT_, 320>>>(p_t, W_fc, b_fc, out);
}

// round 3
// speedup vs baseline: 1.7461x; 1.7461x over previous
#include <cuda_runtime.h>
#include <cuda_bf16.h>
#include <math.h>
#include <stdint.h>

// ---------------- problem constants ----------------
#define BT_   1024          // batch
#define CH_   3
#define AW_   64
#define BH_   64
#define NF_   16
#define HD_   1024
#define IN_   768
#define GATE_ 4096
#define TSTEPS_ 16

// ---------------- persistent scratch ----------------
__device__ float g_h[BT_ * HD_];
__device__ float g_c[BT_ * HD_];
__device__ float g_r[BT_ * IN_];
__device__ float g_gates[BT_ * GATE_];
__device__ float g_Fx[BT_ * NF_ * AW_];
__device__ float g_Fy[BT_ * NF_ * BH_];
__device__ float g_gamma[BT_];
__device__ float g_t[BT_ * HD_];

__device__ __nv_bfloat16 g_Wih_hi[GATE_ * IN_];
__device__ __nv_bfloat16 g_Wih_lo[GATE_ * IN_];
__device__ __nv_bfloat16 g_Whh_hi[GATE_ * HD_];
__device__ __nv_bfloat16 g_Whh_lo[GATE_ * HD_];
__device__ float g_bias[GATE_];

// ---------------- helpers ----------------
__device__ __forceinline__ uint32_t smem_to_u32(const void* p) {
    uint32_t a;
    asm("{ .reg .u64 t; cvta.to.shared.u64 t, %1; cvt.u32.u64 %0, t; }" : "=r"(a) : "l"(p));
    return a;
}
__device__ __forceinline__ void ldsm4(uint32_t* r, uint32_t addr) {
    asm volatile("ldmatrix.sync.aligned.m8n8.x4.shared.b16 {%0,%1,%2,%3}, [%4];"
        : "=r"(r[0]), "=r"(r[1]), "=r"(r[2]), "=r"(r[3]) : "r"(addr));
}
__device__ __forceinline__ void mma_bf16(float* d, const uint32_t* a, const uint32_t* b) {
    asm volatile("mma.sync.aligned.m16n8k16.row.col.f32.bf16.bf16.f32 "
        "{%0,%1,%2,%3}, {%4,%5,%6,%7}, {%8,%9}, {%0,%1,%2,%3};"
        : "+f"(d[0]), "+f"(d[1]), "+f"(d[2]), "+f"(d[3])
        : "r"(a[0]), "r"(a[1]), "r"(a[2]), "r"(a[3]), "r"(b[0]), "r"(b[1]));
}
__device__ __forceinline__ void split2(float a, float b, unsigned& hi, unsigned& lo) {
    __nv_bfloat16 ha = __float2bfloat16_rn(a), hb = __float2bfloat16_rn(b);
    float ra = a - __bfloat162float(ha);
    float rb = b - __bfloat162float(hb);
    __nv_bfloat16 la = __float2bfloat16_rn(ra), lb = __float2bfloat16_rn(rb);
    hi = (unsigned)__bfloat16_as_ushort(ha) | ((unsigned)__bfloat16_as_ushort(hb) << 16);
    lo = (unsigned)__bfloat16_as_ushort(la) | ((unsigned)__bfloat16_as_ushort(lb) << 16);
}

// ---------------- weight prep ----------------
__global__ void prep_kernel(const float* __restrict__ W_ih, const float* __restrict__ W_hh,
                            const float* __restrict__ b_ih, const float* __restrict__ b_hh) {
    const int T1 = GATE_ * IN_;
    const int T2 = GATE_ * HD_;
    int i = blockIdx.x * blockDim.x + threadIdx.x;
    if (i < T1) {
        float v = W_ih[i];
        __nv_bfloat16 hb = __float2bfloat16_rn(v);
        g_Wih_hi[i] = hb;
        g_Wih_lo[i] = __float2bfloat16_rn(v - __bfloat162float(hb));
    } else if (i < T1 + T2) {
        int j = i - T1;
        float v = W_hh[j];
        __nv_bfloat16 hb = __float2bfloat16_rn(v);
        g_Whh_hi[j] = hb;
        g_Whh_lo[j] = __float2bfloat16_rn(v - __bfloat162float(hb));
    } else if (i < T1 + T2 + GATE_) {
        int j = i - T1 - T2;
        g_bias[j] = b_ih[j] + b_hh[j];
    }
}

// ---------------- HMMA gate GEMM ----------------
// gates[1024 x 4096] = [r | h] @ [W_ih | W_hh]^T + bias  via bf16 hi/lo split (3 terms)
// CTA tile 128x128, 8 warps (2x4), warp tile 64x32, K-chunk 32, 56 chunks.
#define KCHUNKS 56
#define LDS_ROW 80               // 32 bf16 = 64B data, padded to 80B (conflict-free ldmatrix)
#define A_HI 0
#define A_LO 10240
#define W_HI 20480
#define W_LO 30720
#define STAGE_BYTES 40960
#define GEMM_SMEM (2 * STAGE_BYTES)

struct Pref { float4 av[4]; uint4 wh[2]; uint4 wl[2]; };

__device__ __forceinline__ void load_chunk(int kt, int m0, int n0, int arow, int acol,
                                           const float* __restrict__ r,
                                           const float* __restrict__ h, Pref& p) {
    const float* Ap; const __nv_bfloat16 *Wh, *Wl; int ldA, kk;
    if (kt < 24) { Ap = r; Wh = g_Wih_hi; Wl = g_Wih_lo; ldA = IN_; kk = kt * 32; }
    else         { Ap = h; Wh = g_Whh_hi; Wl = g_Whh_lo; ldA = HD_; kk = (kt - 24) * 32; }
    const float* as = Ap + (size_t)(m0 + arow) * ldA + kk + acol;
    p.av[0] = *reinterpret_cast<const float4*>(as);
    p.av[1] = *reinterpret_cast<const float4*>(as + 4);
    p.av[2] = *reinterpret_cast<const float4*>(as + 8);
    p.av[3] = *reinterpret_cast<const float4*>(as + 12);
    const __nv_bfloat16* wsh = Wh + (size_t)(n0 + arow) * ldA + kk + acol;
    const __nv_bfloat16* wsl = Wl + (size_t)(n0 + arow) * ldA + kk + acol;
    p.wh[0] = *reinterpret_cast<const uint4*>(wsh);
    p.wh[1] = *reinterpret_cast<const uint4*>(wsh + 8);
    p.wl[0] = *reinterpret_cast<const uint4*>(wsl);
    p.wl[1] = *reinterpret_cast<const uint4*>(wsl + 8);
}

__device__ __forceinline__ void store_chunk(char* stage, int arow, int acol, const Pref& p) {
    uint4 h0, h1, l0, l1;
    split2(p.av[0].x, p.av[0].y, h0.x, l0.x);
    split2(p.av[0].z, p.av[0].w, h0.y, l0.y);
    split2(p.av[1].x, p.av[1].y, h0.z, l0.z);
    split2(p.av[1].z, p.av[1].w, h0.w, l0.w);
    split2(p.av[2].x, p.av[2].y, h1.x, l1.x);
    split2(p.av[2].z, p.av[2].w, h1.y, l1.y);
    split2(p.av[3].x, p.av[3].y, h1.z, l1.z);
    split2(p.av[3].z, p.av[3].w, h1.w, l1.w);
    uint32_t ab = arow * LDS_ROW + acol * 2;
    *reinterpret_cast<uint4*>(stage + A_HI + ab)      = h0;
    *reinterpret_cast<uint4*>(stage + A_HI + ab + 16) = h1;
    *reinterpret_cast<uint4*>(stage + A_LO + ab)      = l0;
    *reinterpret_cast<uint4*>(stage + A_LO + ab + 16) = l1;
    *reinterpret_cast<uint4*>(stage + W_HI + ab)      = p.wh[0];
    *reinterpret_cast<uint4*>(stage + W_HI + ab + 16) = p.wh[1];
    *reinterpret_cast<uint4*>(stage + W_LO + ab)      = p.wl[0];
    *reinterpret_cast<uint4*>(stage + W_LO + ab + 16) = p.wl[1];
}

__global__ __launch_bounds__(256)
void gate_gemm_mma(const float* __restrict__ r, const float* __restrict__ h,
                   float* __restrict__ gates) {
    extern __shared__ char smem[];
    const uint32_t sb = smem_to_u32(smem);
    const int tid = threadIdx.x;
    const int lane = tid & 31;
    const int wid = tid >> 5;
    const int warp_m = wid >> 2;     // 0..1
    const int warp_n = wid & 3;      // 0..3
    const int n0 = blockIdx.x * 128;
    const int m0 = blockIdx.y * 128;
    const int arow = tid >> 1;       // 0..127
    const int acol = (tid & 1) * 16; // 0 or 16 (elements)

    float acc[4][4][4];
    #pragma unroll
    for (int i = 0; i < 4; i++)
        #pragma unroll
        for (int j = 0; j < 4; j++)
            #pragma unroll
            for (int k = 0; k < 4; k++) acc[i][j][k] = 0.f;

    Pref p;
    load_chunk(0, m0, n0, arow, acol, r, h, p);
    store_chunk(smem, arow, acol, p);
    __syncthreads();

    for (int kt = 0; kt < KCHUNKS; kt++) {
        const int s = kt & 1;
        if (kt + 1 < KCHUNKS) load_chunk(kt + 1, m0, n0, arow, acol, r, h, p);

        const uint32_t sA = sb + s * STAGE_BYTES;
        #pragma unroll
        for (int k16 = 0; k16 < 2; k16++) {
            uint32_t ah[4][4], al[4][4];
            #pragma unroll
            for (int mt = 0; mt < 4; mt++) {
                uint32_t row = warp_m * 64 + mt * 16 + (lane & 15);
                uint32_t ad = sA + A_HI + row * LDS_ROW + k16 * 32 + ((lane >> 4) * 16);
                ldsm4(ah[mt], ad);
                ldsm4(al[mt], ad + (A_LO - A_HI));
            }
            uint32_t wf[4][2];
            // hi weights
            #pragma unroll
            for (int g = 0; g < 2; g++) {
                uint32_t rown = warp_n * 32 + g * 16 + (lane & 7) + (lane >> 4) * 8;
                uint32_t wd = sA + W_HI + rown * LDS_ROW +
                              (k16 * 16 + ((lane >> 3) & 1) * 8) * 2;
                uint32_t t4[4];
                ldsm4(t4, wd);
                wf[2 * g][0] = t4[0]; wf[2 * g][1] = t4[1];
                wf[2 * g + 1][0] = t4[2]; wf[2 * g + 1][1] = t4[3];
            }
            #pragma unroll
            for (int mt = 0; mt < 4; mt++)
                #pragma unroll
                for (int nt = 0; nt < 4; nt++)
                    mma_bf16(acc[mt][nt], ah[mt], wf[nt]);
            #pragma unroll
            for (int mt = 0; mt < 4; mt++)
                #pragma unroll
                for (int nt = 0; nt < 4; nt++)
                    mma_bf16(acc[mt][nt], al[mt], wf[nt]);
            // lo weights
            #pragma unroll
            for (int g = 0; g < 2; g++) {
                uint32_t rown = warp_n * 32 + g * 16 + (lane & 7) + (lane >> 4) * 8;
                uint32_t wd = sA + W_LO + rown * LDS_ROW +
                              (k16 * 16 + ((lane >> 3) & 1) * 8) * 2;
                uint32_t t4[4];
                ldsm4(t4, wd);
                wf[2 * g][0] = t4[0]; wf[2 * g][1] = t4[1];
                wf[2 * g + 1][0] = t4[2]; wf[2 * g + 1][1] = t4[3];
            }
            #pragma unroll
            for (int mt = 0; mt < 4; mt++)
                #pragma unroll
                for (int nt = 0; nt < 4; nt++)
                    mma_bf16(acc[mt][nt], ah[mt], wf[nt]);
        }

        if (kt + 1 < KCHUNKS) store_chunk(smem + ((kt + 1) & 1) * STAGE_BYTES, arow, acol, p);
        __syncthreads();
    }

    // epilogue: bias + store
    #pragma unroll
    for (int mt = 0; mt < 4; mt++) {
        int row0 = m0 + warp_m * 64 + mt * 16 + (lane >> 2);
        #pragma unroll
        for (int nt = 0; nt < 4; nt++) {
            int col = n0 + warp_n * 32 + nt * 8 + (lane & 3) * 2;
            float2 bv = *reinterpret_cast<const float2*>(&g_bias[col]);
            float2 v0 = make_float2(acc[mt][nt][0] + bv.x, acc[mt][nt][1] + bv.y);
            float2 v1 = make_float2(acc[mt][nt][2] + bv.x, acc[mt][nt][3] + bv.y);
            *reinterpret_cast<float2*>(gates + (size_t)row0 * GATE_ + col) = v0;
            *reinterpret_cast<float2*>(gates + (size_t)(row0 + 8) * GATE_ + col) = v1;
        }
    }
}

// ---------------- zero h and c ----------------
__global__ void zero_hc_kernel() {
    int i = blockIdx.x * blockDim.x + threadIdx.x;
    if (i < BT_ * HD_) { g_h[i] = 0.f; g_c[i] = 0.f; }
}

// ---------------- attention params + filterbanks ----------------
__global__ void att_kernel(const float* __restrict__ h,
                           const float* __restrict__ W_att,
                           const float* __restrict__ b_att,
                           float* __restrict__ Fx,
                           float* __restrict__ Fy,
                           float* __restrict__ gamma) {
    const int b   = blockIdx.x;
    const int tid = threadIdx.x;

    __shared__ float red[5][256];
    __shared__ float params[5];
    __shared__ float F[16][64];
    __shared__ float rnorm[16];

    float a0 = 0.f, a1 = 0.f, a2 = 0.f, a3 = 0.f, a4 = 0.f;
    const float* hb = h + b * HD_;
    for (int k = tid; k < HD_; k += 256) {
        float hv = hb[k];
        a0 += hv * W_att[0 * HD_ + k];
        a1 += hv * W_att[1 * HD_ + k];
        a2 += hv * W_att[2 * HD_ + k];
        a3 += hv * W_att[3 * HD_ + k];
        a4 += hv * W_att[4 * HD_ + k];
    }
    red[0][tid] = a0; red[1][tid] = a1; red[2][tid] = a2; red[3][tid] = a3; red[4][tid] = a4;
    __syncthreads();
    for (int s = 128; s > 0; s >>= 1) {
        if (tid < s) {
            #pragma unroll
            for (int j = 0; j < 5; j++) red[j][tid] += red[j][tid + s];
        }
        __syncthreads();
    }
    if (tid < 5) params[tid] = red[tid][0] + b_att[tid];
    __syncthreads();

    const float gx     = 32.5f * (params[0] + 1.0f);
    const float gy     = 32.5f * (params[1] + 1.0f);
    const float sigma2 = expf(params[2]);
    const float delta  = (63.0f / 15.0f) * expf(params[3]);
    if (tid == 0) gamma[b] = expf(params[4]);
    const float inv2s = 1.0f / (2.0f * sigma2);

    for (int idx = tid; idx < NF_ * AW_; idx += 256) {
        int i = idx >> 6, a = idx & 63;
        float mu = gx + ((float)i - 8.5f) * delta;
        float d  = (float)a - mu;
        F[i][a]  = expf(-d * d * inv2s);
    }
    __syncthreads();
    if (tid < 16) {
        float s = 0.f;
        for (int a = 0; a < 64; a++) s += F[tid][a];
        rnorm[tid] = 1.0f / (s + 1e-8f);
    }
    __syncthreads();
    for (int idx = tid; idx < NF_ * AW_; idx += 256) {
        int i = idx >> 6, a = idx & 63;
        Fx[b * NF_ * AW_ + idx] = F[i][a] * rnorm[i];
    }
    __syncthreads();

    for (int idx = tid; idx < NF_ * BH_; idx += 256) {
        int i = idx >> 6, a = idx & 63;
        float mu = gy + ((float)i - 8.5f) * delta;
        float d  = (float)a - mu;
        F[i][a]  = expf(-d * d * inv2s);
    }
    __syncthreads();
    if (tid < 16) {
        float s = 0.f;
        for (int a = 0; a < 64; a++) s += F[tid][a];
        rnorm[tid] = 1.0f / (s + 1e-8f);
    }
    __syncthreads();
    for (int idx = tid; idx < NF_ * BH_; idx += 256) {
        int i = idx >> 6, a = idx & 63;
        Fy[b * NF_ * BH_ + idx] = F[i][a] * rnorm[i];
    }
}

// ---------------- glimpse, channel-parallel ----------------
__global__ void glimpse_kernel(const float* __restrict__ x,
                               const float* __restrict__ Fx,
                               const float* __restrict__ Fy,
                               const float* __restrict__ gamma,
                               float* __restrict__ r) {
    const int b   = blockIdx.x;
    const int c   = blockIdx.y;
    const int tid = threadIdx.x;

    __shared__ float sFy[NF_ * BH_];
    __shared__ float sFx[NF_][AW_ + 1];
    __shared__ float simg[BH_ * AW_];
    __shared__ float stmp[NF_ * AW_];

    for (int idx = tid; idx < NF_ * BH_; idx += 256) sFy[idx] = Fy[b * NF_ * BH_ + idx];
    for (int idx = tid; idx < NF_ * AW_; idx += 256) {
        int i = idx >> 6, a = idx & 63;
        sFx[i][a] = Fx[b * NF_ * AW_ + idx];
    }
    const float gam = gamma[b];

    const float* xc = x + ((size_t)(b * CH_ + c)) * (BH_ * AW_);
    for (int idx = tid; idx < BH_ * AW_; idx += 256) simg[idx] = xc[idx];
    __syncthreads();

    for (int idx = tid; idx < NF_ * AW_; idx += 256) {
        int n = idx >> 6, a = idx & 63;
        float s = 0.f;
        #pragma unroll 8
        for (int y = 0; y < BH_; y++) s += sFy[n * BH_ + y] * simg[y * AW_ + a];
        stmp[idx] = s;
    }
    __syncthreads();
    {
        int n = tid >> 4, xo = tid & 15;
        float s = 0.f;
        #pragma unroll 8
        for (int a = 0; a < AW_; a++) s += stmp[n * AW_ + a] * sFx[xo][a];
        r[b * IN_ + c * (NF_ * NF_) + n * NF_ + xo] = s * gam;
    }
}

// ---------------- SIMT GEMM (fc0 only) ----------------
template <bool RELU>
__global__ __launch_bounds__(256, 2)
void gemm_nt(const float* __restrict__ A0, int K0, const float* __restrict__ W0,
             const float* __restrict__ bias0,
             float* __restrict__ C, int M, int Nn) {
    __shared__ float As[16][128];
    __shared__ float Bs[16][128];

    const int tid = threadIdx.x;
    const int m0  = blockIdx.y * 128;
    const int n0  = blockIdx.x * 128;
    const int tx  = tid & 15;
    const int ty  = tid >> 4;
    const int lrow = tid >> 1;
    const int lq   = (tid & 1) * 2;

    float acc[8][8];
    #pragma unroll
    for (int i = 0; i < 8; i++)
        #pragma unroll
        for (int j = 0; j < 8; j++) acc[i][j] = 0.f;

    for (int kt = 0; kt < K0; kt += 16) {
        #pragma unroll
        for (int qq = 0; qq < 2; qq++) {
            int q = lq + qq;
            float4 va = *reinterpret_cast<const float4*>(A0 + (m0 + lrow) * K0 + kt + q * 4);
            As[q * 4 + 0][lrow] = va.x;
            As[q * 4 + 1][lrow] = va.y;
            As[q * 4 + 2][lrow] = va.z;
            As[q * 4 + 3][lrow] = va.w;
            float4 vb = *reinterpret_cast<const float4*>(W0 + (n0 + lrow) * K0 + kt + q * 4);
            Bs[q * 4 + 0][lrow] = vb.x;
            Bs[q * 4 + 1][lrow] = vb.y;
            Bs[q * 4 + 2][lrow] = vb.z;
            Bs[q * 4 + 3][lrow] = vb.w;
        }
        __syncthreads();

        #pragma unroll
        for (int k = 0; k < 16; k++) {
            float ra[8], rb[8];
            #pragma unroll
            for (int i = 0; i < 8; i++) ra[i] = As[k][ty * 8 + i];
            #pragma unroll
            for (int j = 0; j < 8; j++) rb[j] = Bs[k][tx * 8 + j];
            #pragma unroll
            for (int i = 0; i < 8; i++)
                #pragma unroll
                for (int j = 0; j < 8; j++) acc[i][j] += ra[i] * rb[j];
        }
        __syncthreads();
    }

    #pragma unroll
    for (int i = 0; i < 8; i++) {
        int m = m0 + ty * 8 + i;
        #pragma unroll
        for (int jv = 0; jv < 2; jv++) {
            int n = n0 + tx * 8 + jv * 4;
            float4 v;
            float* vp = &v.x;
            #pragma unroll
            for (int u = 0; u < 4; u++) {
                float t = acc[i][jv * 4 + u] + bias0[n + u];
                if (RELU) t = fmaxf(t, 0.f);
                vp[u] = t;
            }
            *reinterpret_cast<float4*>(C + (size_t)m * Nn + n) = v;
        }
    }
}

// ---------------- LSTM pointwise update ----------------
__global__ void lstm_kernel(const float* __restrict__ gates,
                            float* __restrict__ c, float* __restrict__ h) {
    int idx = blockIdx.x * blockDim.x + threadIdx.x;
    if (idx >= BT_ * HD_) return;
    int b = idx >> 10, j = idx & 1023;
    const float* g = gates + b * GATE_;
    float ig = g[j];
    float fg = g[HD_ + j];
    float gg = g[2 * HD_ + j];
    float og = g[3 * HD_ + j];
    float si = 1.f / (1.f + expf(-ig));
    float sf = 1.f / (1.f + expf(-fg));
    float so = 1.f / (1.f + expf(-og));
    float tg = tanhf(gg);
    float cn = sf * c[idx] + si * tg;
    c[idx] = cn;
    h[idx] = so * tanhf(cn);
}

// ---------------- final small fc ----------------
__global__ void fc_kernel(const float* __restrict__ t,
                          const float* __restrict__ W_fc,
                          const float* __restrict__ b_fc,
                          float* __restrict__ out) {
    int b    = blockIdx.x;
    int w    = threadIdx.x >> 5;
    int lane = threadIdx.x & 31;
    const float* tb = t + b * HD_;
    const float* wr = W_fc + w * HD_;
    float s = 0.f;
    for (int k = lane; k < HD_; k += 32) s += tb[k] * wr[k];
    #pragma unroll
    for (int off = 16; off; off >>= 1) s += __shfl_down_sync(0xffffffffu, s, off);
    if (lane == 0) out[b * 10 + w] = s + b_fc[w];
}

// ---------------- host launch ----------------
extern "C" void kernel_launch(void* const* d_in, const int* in_sizes, int n_in,
                              void* d_out, int out_size) {
    const float* x     = (const float*)d_in[0];
    const float* W_att = (const float*)d_in[1];
    const float* b_att = (const float*)d_in[2];
    const float* W_ih  = (const float*)d_in[3];
    const float* W_hh  = (const float*)d_in[4];
    const float* b_ih  = (const float*)d_in[5];
    const float* b_hh  = (const float*)d_in[6];
    const float* W_fc0 = (const float*)d_in[7];
    const float* b_fc0 = (const float*)d_in[8];
    const float* W_fc  = (const float*)d_in[9];
    const float* b_fc  = (const float*)d_in[10];
    float* out = (float*)d_out;

    static float *p_h = nullptr, *p_c, *p_r, *p_gates, *p_Fx, *p_Fy, *p_gamma, *p_t;
    static bool attr_done = false;
    if (!p_h) {
        cudaGetSymbolAddress((void**)&p_h,     g_h);
        cudaGetSymbolAddress((void**)&p_c,     g_c);
        cudaGetSymbolAddress((void**)&p_r,     g_r);
        cudaGetSymbolAddress((void**)&p_gates, g_gates);
        cudaGetSymbolAddress((void**)&p_Fx,    g_Fx);
        cudaGetSymbolAddress((void**)&p_Fy,    g_Fy);
        cudaGetSymbolAddress((void**)&p_gamma, g_gamma);
        cudaGetSymbolAddress((void**)&p_t,     g_t);
    }
    if (!attr_done) {
        cudaFuncSetAttribute(gate_gemm_mma,
                             cudaFuncAttributeMaxDynamicSharedMemorySize, GEMM_SMEM);
        attr_done = true;
    }

    {
        const int total = GATE_ * IN_ + GATE_ * HD_ + GATE_;
        prep_kernel<<<(total + 255) / 256, 256>>>(W_ih, W_hh, b_ih, b_hh);
    }

    zero_hc_kernel<<<(BT_ * HD_ + 255) / 256, 256>>>();

    for (int step = 0; step < TSTEPS_; step++) {
        att_kernel<<<BT_, 256>>>(p_h, W_att, b_att, p_Fx, p_Fy, p_gamma);
        glimpse_kernel<<<dim3(BT_, CH_), 256>>>(x, p_Fx, p_Fy, p_gamma, p_r);
        gate_gemm_mma<<<dim3(GATE_ / 128, BT_ / 128), 256, GEMM_SMEM>>>(p_r, p_h, p_gates);
        lstm_kernel<<<(BT_ * HD_) / 256, 256>>>(p_gates, p_c, p_h);
    }

    gemm_nt<true><<<dim3(HD_ / 128, BT_ / 128), 256>>>(p_h, HD_, W_fc0, b_fc0, p_t, BT_, HD_);

    fc_kernel<<<BT_, 320>>>(p_t, W_fc, b_fc, out);
}